// round 4
// baseline (speedup 1.0000x reference)
#include <cuda_runtime.h>
#include <cuda_bf16.h>
#include <math.h>

// Problem constants
constexpr int B   = 8;
constexpr int R   = 128;
constexpr int H   = 256;
constexpr int IND = 512;
constexpr int L   = 3;
constexpr int NH  = 4;
constexpr int DH  = 64;

constexpr int SZ = B * R * H;  // 262144
constexpr int HH = H * H;

// Scratch layout inside one big device buffer
constexpr int OFF_H    = 0;
constexpr int OFF_AACT = SZ;
constexpr int OFF_BB   = 2 * SZ;
constexpr int OFF_AGG  = 3 * SZ;
constexpr int OFF_HU   = 4 * SZ;
constexpr int OFF_UPRE = 5 * SZ;
constexpr int OFF_U    = 6 * SZ;
constexpr int OFF_Q    = 7 * SZ;
constexpr int OFF_K    = 8 * SZ;
constexpr int OFF_V    = 9 * SZ;
constexpr int OFF_AO   = 10 * SZ;
constexpr int OFF_ADJ  = 11 * SZ;                 // R*R
constexpr int OFF_RS   = OFF_ADJ + R * R;         // R
constexpr int OFF_W2U  = OFF_RS + R;              // L*H*H
constexpr int OFF_C2   = OFF_W2U + L * HH;        // L*H
constexpr int TOTAL    = OFF_C2 + L * H;

__device__ float g_buf[TOTAL];

typedef unsigned long long u64;

__device__ __forceinline__ u64 pack2(float x) {
    u64 r; asm("mov.b64 %0, {%1, %1};" : "=l"(r) : "f"(x)); return r;
}
__device__ __forceinline__ void fma2(u64& d, u64 a, u64 b) {
    asm("fma.rn.f32x2 %0, %1, %2, %0;" : "+l"(d) : "l"(a), "l"(b));
}
__device__ __forceinline__ float2 unpack2(u64 v) {
    float2 f; asm("mov.b64 {%0, %1}, %2;" : "=f"(f.x), "=f"(f.y) : "l"(v)); return f;
}

// ---------------------------------------------------------------------------
// Fused setup: blocks 0..127 -> prep_A ; 128..135 -> h0 ; 136..138 -> c2
__global__ __launch_bounds__(256) void setup_kernel(
    const float* __restrict__ rule_adj, float* __restrict__ A, float* __restrict__ rowsum,
    const float* __restrict__ x, const float* __restrict__ We,
    const float* __restrict__ be, float* __restrict__ h,
    const float* __restrict__ msg_b2, const float* __restrict__ upd_W1,
    float* __restrict__ c2)
{
    int bid = blockIdx.x, t = threadIdx.x;
    if (bid < 128) {
        // prep_A: row i = bid, 128 active threads
        if (t < 128) {
            int i = bid, j = t;
            float v = rule_adj[i * R + j];
            float s = 1.f / (1.f + expf(-v));
            if (i == j) s = 0.f;
            A[i * R + j] = s;
            __shared__ float red[4];
            float tt = s;
            for (int o = 16; o; o >>= 1) tt += __shfl_xor_sync(0xffffffffu, tt, o);
            if ((j & 31) == 0) red[j >> 5] = tt;
            __syncthreads();
            if (j == 0) rowsum[i] = red[0] + red[1] + red[2] + red[3];
        }
    } else if (bid < 136) {
        // h0 for batch b
        __shared__ float xs[IND];
        int b = bid - 128;
        xs[t]       = x[b * IND + t];
        xs[t + 256] = x[b * IND + 256 + t];
        __syncthreads();
        float acc = be[t];
        #pragma unroll 8
        for (int k = 0; k < IND; k++) acc += xs[k] * We[k * H + t];
        for (int r = 0; r < R; r++) h[(b * R + r) * H + t] = acc;
    } else {
        // c2[l] = msg_b2[l] @ upd_W1b[l]
        __shared__ float bs[H];
        int l = bid - 136;
        bs[t] = msg_b2[l * H + t];
        __syncthreads();
        const float* W = upd_W1 + l * 2 * HH + HH;
        float acc = 0.f;
        #pragma unroll 8
        for (int k = 0; k < H; k++) acc += bs[k] * W[k * H + t];
        c2[l * H + t] = acc;
    }
}

// ---------------------------------------------------------------------------
// GEMM: C = act(A@W [+ addend] [+ bias[n]] [+ rowv[m&127]*colv[n]])
// N = K = 256 fixed. BM=32, BN=64, BK=32, 128 threads, 2m x 8n outputs/thread.
// Double-buffered smem, packed fma.rn.f32x2 (bit-identical rounding to FFMA).
// Up to 3 independent jobs via blockIdx.z.
struct GemmJob {
    const float* A;
    const float* W;
    const float* bias;    // [256] or null
    const float* rowv;    // [128] or null (indexed m & 127)
    const float* colv;    // [256] (with rowv)
    const float* addend;  // [M,256] or null
    float* C;
    int relu;
};

__global__ __launch_bounds__(128) void gemm_kernel(GemmJob j0, GemmJob j1, GemmJob j2) {
    __shared__ float As[2][32][33];
    __shared__ float Ws[2][32][64];

    GemmJob job = (blockIdx.z == 0) ? j0 : ((blockIdx.z == 1) ? j1 : j2);
    const float* __restrict__ A = job.A;
    const float* __restrict__ W = job.W;

    const int m0 = blockIdx.y * 32, n0 = blockIdx.x * 64;
    const int t = threadIdx.x;

    // compute mapping: 2 rows x 8 cols per thread
    const int mg2 = (t >> 3) * 2;     // 0,2,..,30
    const int ng8 = (t & 7) * 8;      // 0,8,..,56

    // A loads: 2 float4/thread (32 rows x 32 k)
    const int ar = t >> 2, ac = (t & 3) * 4;
    // W loads: 4 float4/thread (32 rows x 64 n)
    const int wr = t >> 4, wc = (t & 15) * 4;

    u64 acc[8];
    #pragma unroll
    for (int i = 0; i < 8; i++) acc[i] = 0ull;

    float4 aR0, aR1, wR0, wR1, wR2, wR3;

    // prologue: tile 0
    aR0 = *(const float4*)&A[(m0 + ar) * 256 + ac];
    aR1 = *(const float4*)&A[(m0 + ar) * 256 + 16 + ac];
    wR0 = *(const float4*)&W[(wr +  0) * 256 + n0 + wc];
    wR1 = *(const float4*)&W[(wr +  8) * 256 + n0 + wc];
    wR2 = *(const float4*)&W[(wr + 16) * 256 + n0 + wc];
    wR3 = *(const float4*)&W[(wr + 24) * 256 + n0 + wc];
    {
        As[0][ac + 0][ar] = aR0.x; As[0][ac + 1][ar] = aR0.y;
        As[0][ac + 2][ar] = aR0.z; As[0][ac + 3][ar] = aR0.w;
        As[0][ac + 16][ar] = aR1.x; As[0][ac + 17][ar] = aR1.y;
        As[0][ac + 18][ar] = aR1.z; As[0][ac + 19][ar] = aR1.w;
        *(float4*)&Ws[0][wr +  0][wc] = wR0;
        *(float4*)&Ws[0][wr +  8][wc] = wR1;
        *(float4*)&Ws[0][wr + 16][wc] = wR2;
        *(float4*)&Ws[0][wr + 24][wc] = wR3;
    }
    __syncthreads();

    #pragma unroll 1
    for (int t8 = 0; t8 < 8; t8++) {
        const int cur = t8 & 1;
        const bool has_next = (t8 < 7);
        if (has_next) {
            const int k0 = (t8 + 1) * 32;
            aR0 = *(const float4*)&A[(m0 + ar) * 256 + k0 + ac];
            aR1 = *(const float4*)&A[(m0 + ar) * 256 + k0 + 16 + ac];
            wR0 = *(const float4*)&W[(k0 + wr +  0) * 256 + n0 + wc];
            wR1 = *(const float4*)&W[(k0 + wr +  8) * 256 + n0 + wc];
            wR2 = *(const float4*)&W[(k0 + wr + 16) * 256 + n0 + wc];
            wR3 = *(const float4*)&W[(k0 + wr + 24) * 256 + n0 + wc];
        }
        #pragma unroll
        for (int kk = 0; kk < 32; kk++) {
            const float* wsr = &Ws[cur][kk][0];
            ulonglong2 wv0 = *(const ulonglong2*)(wsr + ng8);
            ulonglong2 wv1 = *(const ulonglong2*)(wsr + ng8 + 4);
            u64 pa0 = pack2(As[cur][kk][mg2]);
            u64 pa1 = pack2(As[cur][kk][mg2 + 1]);
            fma2(acc[0], pa0, wv0.x); fma2(acc[1], pa0, wv0.y);
            fma2(acc[2], pa0, wv1.x); fma2(acc[3], pa0, wv1.y);
            fma2(acc[4], pa1, wv0.x); fma2(acc[5], pa1, wv0.y);
            fma2(acc[6], pa1, wv1.x); fma2(acc[7], pa1, wv1.y);
        }
        if (has_next) {
            const int nxt = cur ^ 1;
            As[nxt][ac + 0][ar] = aR0.x; As[nxt][ac + 1][ar] = aR0.y;
            As[nxt][ac + 2][ar] = aR0.z; As[nxt][ac + 3][ar] = aR0.w;
            As[nxt][ac + 16][ar] = aR1.x; As[nxt][ac + 17][ar] = aR1.y;
            As[nxt][ac + 18][ar] = aR1.z; As[nxt][ac + 19][ar] = aR1.w;
            *(float4*)&Ws[nxt][wr +  0][wc] = wR0;
            *(float4*)&Ws[nxt][wr +  8][wc] = wR1;
            *(float4*)&Ws[nxt][wr + 16][wc] = wR2;
            *(float4*)&Ws[nxt][wr + 24][wc] = wR3;
        }
        __syncthreads();
    }

    // epilogue
    float4 bi0, bi1, cv0, cv1;
    if (job.bias) {
        bi0 = *(const float4*)&job.bias[n0 + ng8];
        bi1 = *(const float4*)&job.bias[n0 + ng8 + 4];
    }
    if (job.rowv) {
        cv0 = *(const float4*)&job.colv[n0 + ng8];
        cv1 = *(const float4*)&job.colv[n0 + ng8 + 4];
    }
    #pragma unroll
    for (int i = 0; i < 2; i++) {
        const int m = m0 + mg2 + i;
        float2 p0 = unpack2(acc[i * 4 + 0]);
        float2 p1 = unpack2(acc[i * 4 + 1]);
        float2 p2 = unpack2(acc[i * 4 + 2]);
        float2 p3 = unpack2(acc[i * 4 + 3]);
        float4 v0 = make_float4(p0.x, p0.y, p1.x, p1.y);
        float4 v1 = make_float4(p2.x, p2.y, p3.x, p3.y);
        if (job.addend) {
            float4 a0 = *(const float4*)&job.addend[m * 256 + n0 + ng8];
            float4 a1 = *(const float4*)&job.addend[m * 256 + n0 + ng8 + 4];
            v0.x += a0.x; v0.y += a0.y; v0.z += a0.z; v0.w += a0.w;
            v1.x += a1.x; v1.y += a1.y; v1.z += a1.z; v1.w += a1.w;
        }
        if (job.bias) {
            v0.x += bi0.x; v0.y += bi0.y; v0.z += bi0.z; v0.w += bi0.w;
            v1.x += bi1.x; v1.y += bi1.y; v1.z += bi1.z; v1.w += bi1.w;
        }
        if (job.rowv) {
            float rv = job.rowv[m & (R - 1)];
            v0.x += rv * cv0.x; v0.y += rv * cv0.y; v0.z += rv * cv0.z; v0.w += rv * cv0.w;
            v1.x += rv * cv1.x; v1.y += rv * cv1.y; v1.z += rv * cv1.z; v1.w += rv * cv1.w;
        }
        if (job.relu) {
            v0.x = fmaxf(v0.x, 0.f); v0.y = fmaxf(v0.y, 0.f);
            v0.z = fmaxf(v0.z, 0.f); v0.w = fmaxf(v0.w, 0.f);
            v1.x = fmaxf(v1.x, 0.f); v1.y = fmaxf(v1.y, 0.f);
            v1.z = fmaxf(v1.z, 0.f); v1.w = fmaxf(v1.w, 0.f);
        }
        *(float4*)&job.C[m * 256 + n0 + ng8] = v0;
        *(float4*)&job.C[m * 256 + n0 + ng8 + 4] = v1;
    }
}

// ---------------------------------------------------------------------------
// aggpre[b,i,h] = sum_j A[i,j] * relu(a[b,i,h] + bb[b,j,h])   (b1 folded into bb)
// grid (hc=4, ic=8, b=8) = 256 CTAs, 128 threads. bb tile in smem.
__global__ __launch_bounds__(128) void agg_kernel(
    const float* __restrict__ a, const float* __restrict__ bbg,
    const float* __restrict__ A, float* __restrict__ out)
{
    __shared__ float bbs[128][64];
    int hc = blockIdx.x * 64, ic = blockIdx.y * 16, b = blockIdx.z;
    int t = threadIdx.x;
    const float* bp = bbg + b * R * H;
    for (int idx = t; idx < 2048; idx += 128) {
        int j = idx >> 4, c4 = (idx & 15) * 4;
        *(float4*)&bbs[j][c4] = *(const float4*)&bp[j * H + hc + c4];
    }
    __syncthreads();
    int hl = (t & 15) * 4;
    int i0 = ic + (t >> 4) * 2;
    float4 av0 = *(const float4*)&a[(b * R + i0) * H + hc + hl];
    float4 av1 = *(const float4*)&a[(b * R + i0 + 1) * H + hc + hl];
    float4 ac0 = {0, 0, 0, 0}, ac1 = {0, 0, 0, 0};
    const float* Ar = A + i0 * R;
    #pragma unroll 4
    for (int j = 0; j < R; j++) {
        float4 bv = *(const float4*)&bbs[j][hl];
        float w0 = __ldg(&Ar[j]);
        float w1 = __ldg(&Ar[R + j]);
        ac0.x += w0 * fmaxf(av0.x + bv.x, 0.f);
        ac0.y += w0 * fmaxf(av0.y + bv.y, 0.f);
        ac0.z += w0 * fmaxf(av0.z + bv.z, 0.f);
        ac0.w += w0 * fmaxf(av0.w + bv.w, 0.f);
        ac1.x += w1 * fmaxf(av1.x + bv.x, 0.f);
        ac1.y += w1 * fmaxf(av1.y + bv.y, 0.f);
        ac1.z += w1 * fmaxf(av1.z + bv.z, 0.f);
        ac1.w += w1 * fmaxf(av1.w + bv.w, 0.f);
    }
    *(float4*)&out[(b * R + i0) * H + hc + hl]     = ac0;
    *(float4*)&out[(b * R + i0 + 1) * H + hc + hl] = ac1;
}

// ---------------------------------------------------------------------------
// h = LayerNorm(h + u) * g + beta   (u already contains upd_b2)
__global__ void ln_kernel(float* __restrict__ h, const float* __restrict__ u,
                          const float* __restrict__ gg, const float* __restrict__ bb) {
    __shared__ float red[8];
    int row = blockIdx.x, t = threadIdx.x;
    int o = row * H + t;
    float x = h[o] + u[o];
    float s = x;
    for (int k = 16; k; k >>= 1) s += __shfl_xor_sync(0xffffffffu, s, k);
    if ((t & 31) == 0) red[t >> 5] = s;
    __syncthreads();
    if (t < 32) {
        float v = (t < 8) ? red[t] : 0.f;
        for (int k = 4; k; k >>= 1) v += __shfl_xor_sync(0xffffffffu, v, k);
        if (t == 0) red[0] = v;
    }
    __syncthreads();
    float mu = red[0] * (1.f / H);
    __syncthreads();
    float d = x - mu;
    float q = d * d;
    for (int k = 16; k; k >>= 1) q += __shfl_xor_sync(0xffffffffu, q, k);
    if ((t & 31) == 0) red[t >> 5] = q;
    __syncthreads();
    if (t < 32) {
        float v = (t < 8) ? red[t] : 0.f;
        for (int k = 4; k; k >>= 1) v += __shfl_xor_sync(0xffffffffu, v, k);
        if (t == 0) red[0] = v;
    }
    __syncthreads();
    float var = red[0] * (1.f / H);
    h[o] = d * rsqrtf(var + 1e-5f) * gg[t] + bb[t];
}

// ---------------------------------------------------------------------------
// Multi-head attention for one (b, head, q-chunk of 16 rows). Everything in smem.
__global__ __launch_bounds__(256) void attn_kernel(
    const float* __restrict__ q, const float* __restrict__ k,
    const float* __restrict__ v, float* __restrict__ ao)
{
    __shared__ float ks[128 * 65];   // k tile, pitch 65 (also reused for v, pitch 64)
    __shared__ float qs[16 * 64];
    __shared__ float ls[16 * 128];
    int qc = blockIdx.x, head = blockIdx.y, b = blockIdx.z;
    int t = threadIdx.x;

    const float* kb = k + b * R * H + head * DH;
    for (int idx = t; idx < 128 * 64; idx += 256) {
        int j = idx >> 6, d = idx & 63;
        ks[j * 65 + d] = kb[j * H + d];
    }
    const float* qb = q + (b * R + qc * 16) * H + head * DH;
    for (int idx = t; idx < 16 * 64; idx += 256) {
        int r = idx >> 6, d = idx & 63;
        qs[r * 64 + d] = qb[r * H + d];
    }
    __syncthreads();

    {   // logits
        int j = t & 127, g = t >> 7;
        float acc[8];
        #pragma unroll
        for (int r = 0; r < 8; r++) acc[r] = 0.f;
        for (int d = 0; d < 64; d++) {
            float kv = ks[j * 65 + d];
            #pragma unroll
            for (int r = 0; r < 8; r++) acc[r] += qs[(g * 8 + r) * 64 + d] * kv;
        }
        #pragma unroll
        for (int r = 0; r < 8; r++) ls[(g * 8 + r) * 128 + j] = acc[r] * 0.125f;
    }
    __syncthreads();

    {   // row softmax
        int qr = t >> 4, jc = t & 15;
        float e[8]; float mx = -3e38f;
        #pragma unroll
        for (int jj = 0; jj < 8; jj++) {
            e[jj] = ls[qr * 128 + jc * 8 + jj];
            mx = fmaxf(mx, e[jj]);
        }
        for (int o = 8; o; o >>= 1) mx = fmaxf(mx, __shfl_xor_sync(0xffffffffu, mx, o));
        float s = 0.f;
        #pragma unroll
        for (int jj = 0; jj < 8; jj++) { e[jj] = expf(e[jj] - mx); s += e[jj]; }
        for (int o = 8; o; o >>= 1) s += __shfl_xor_sync(0xffffffffu, s, o);
        float inv = 1.f / s;
        #pragma unroll
        for (int jj = 0; jj < 8; jj++) ls[qr * 128 + jc * 8 + jj] = e[jj] * inv;
    }
    float* vs = ks;
    const float* vb = v + b * R * H + head * DH;
    for (int idx = t; idx < 128 * 64; idx += 256) {
        int j = idx >> 6, d = idx & 63;
        vs[j * 64 + d] = vb[j * H + d];
    }
    __syncthreads();

    {   // out = P @ V
        int qr = t >> 4, d4 = (t & 15) * 4;
        float4 acc = {0, 0, 0, 0};
        for (int j = 0; j < 128; j++) {
            float p = ls[qr * 128 + j];
            float4 vv = *(const float4*)&vs[j * 64 + d4];
            acc.x += p * vv.x; acc.y += p * vv.y;
            acc.z += p * vv.z; acc.w += p * vv.w;
        }
        *(float4*)&ao[(b * R + qc * 16 + qr) * H + head * DH + d4] = acc;
    }
}

// ---------------------------------------------------------------------------
// abar = mean_r ao[b,r,:]; g = abar@Wo + bo; t = relu(g@roW1+rob1);
// logits = t@roW2+rob2; softmax -> out
__global__ void readout_kernel(const float* __restrict__ ao,
                               const float* __restrict__ Wo, const float* __restrict__ bo,
                               const float* __restrict__ roW1, const float* __restrict__ rob1,
                               const float* __restrict__ roW2, const float* __restrict__ rob2,
                               float* __restrict__ out) {
    __shared__ float s0[H], s1[H];
    __shared__ float red[8];
    int b = blockIdx.x, t = threadIdx.x;
    {
        float s = 0.f;
        const float* ap = ao + b * R * H + t;
        for (int r = 0; r < R; r++) s += ap[r * H];
        s0[t] = s * (1.f / R);
    }
    __syncthreads();
    float acc = bo[t];
    #pragma unroll 8
    for (int k = 0; k < H; k++) acc += s0[k] * Wo[k * H + t];
    s1[t] = acc;
    __syncthreads();
    acc = rob1[t];
    #pragma unroll 8
    for (int k = 0; k < H; k++) acc += s1[k] * roW1[k * H + t];
    __syncthreads();
    s0[t] = fmaxf(acc, 0.f);
    __syncthreads();
    float lg = -3e38f;
    if (t < R) {
        lg = rob2[t];
        #pragma unroll 8
        for (int k = 0; k < H; k++) lg += s0[k] * roW2[k * R + t];
    }
    float m = lg;
    for (int k = 16; k; k >>= 1) m = fmaxf(m, __shfl_xor_sync(0xffffffffu, m, k));
    if ((t & 31) == 0) red[t >> 5] = m;
    __syncthreads();
    if (t < 32) {
        float v = (t < 8) ? red[t] : -3e38f;
        for (int k = 4; k; k >>= 1) v = fmaxf(v, __shfl_xor_sync(0xffffffffu, v, k));
        if (t == 0) red[0] = v;
    }
    __syncthreads();
    float mx = red[0];
    __syncthreads();
    float e = (t < R) ? expf(lg - mx) : 0.f;
    float s = e;
    for (int k = 16; k; k >>= 1) s += __shfl_xor_sync(0xffffffffu, s, k);
    if ((t & 31) == 0) red[t >> 5] = s;
    __syncthreads();
    if (t < 32) {
        float v = (t < 8) ? red[t] : 0.f;
        for (int k = 4; k; k >>= 1) v += __shfl_xor_sync(0xffffffffu, v, k);
        if (t == 0) red[0] = v;
    }
    __syncthreads();
    float sum = red[0];
    if (t < R) out[b * R + t] = e / sum;
}

// ---------------------------------------------------------------------------
static inline GemmJob mkjob(const float* A, const float* W, float* C,
                            const float* bias = nullptr, const float* rowv = nullptr,
                            const float* colv = nullptr, const float* addend = nullptr,
                            int relu = 0) {
    GemmJob j;
    j.A = A; j.W = W; j.bias = bias; j.rowv = rowv; j.colv = colv;
    j.addend = addend; j.C = C; j.relu = relu;
    return j;
}

extern "C" void kernel_launch(void* const* d_in, const int* in_sizes, int n_in,
                              void* d_out, int out_size) {
    const float* x       = (const float*)d_in[0];
    const float* We      = (const float*)d_in[1];
    const float* be      = (const float*)d_in[2];
    const float* msg_W1  = (const float*)d_in[3];
    const float* msg_b1  = (const float*)d_in[4];
    const float* msg_W2  = (const float*)d_in[5];
    const float* msg_b2  = (const float*)d_in[6];
    const float* upd_W1  = (const float*)d_in[7];
    const float* upd_b1  = (const float*)d_in[8];
    const float* upd_W2  = (const float*)d_in[9];
    const float* upd_b2  = (const float*)d_in[10];
    const float* ln_g    = (const float*)d_in[11];
    const float* ln_b    = (const float*)d_in[12];
    const float* rule_adj= (const float*)d_in[13];
    const float* Wq      = (const float*)d_in[14];
    const float* bq      = (const float*)d_in[15];
    const float* Wk      = (const float*)d_in[16];
    const float* bk      = (const float*)d_in[17];
    const float* Wv      = (const float*)d_in[18];
    const float* bv      = (const float*)d_in[19];
    const float* Wo      = (const float*)d_in[20];
    const float* bo      = (const float*)d_in[21];
    const float* roW1    = (const float*)d_in[22];
    const float* rob1    = (const float*)d_in[23];
    const float* roW2    = (const float*)d_in[24];
    const float* rob2    = (const float*)d_in[25];
    float* out = (float*)d_out;

    float* base = nullptr;
    cudaGetSymbolAddress((void**)&base, g_buf);
    float* hb    = base + OFF_H;
    float* aact  = base + OFF_AACT;
    float* bbb   = base + OFF_BB;
    float* aggb  = base + OFF_AGG;
    float* hub   = base + OFF_HU;
    float* upreb = base + OFF_UPRE;
    float* ub    = base + OFF_U;
    float* qb    = base + OFF_Q;
    float* kb    = base + OFF_K;
    float* vb    = base + OFF_V;
    float* aob   = base + OFF_AO;
    float* Ab    = base + OFF_ADJ;
    float* rsb   = base + OFF_RS;
    float* w2ub  = base + OFF_W2U;
    float* c2b   = base + OFF_C2;

    const int M = B * R;  // 1024
    dim3 g1(4, M / 32, 1);      // single-job big GEMM (128 CTAs)
    dim3 g3(4, M / 32, 3);      // fused-3 big GEMM (384 CTAs)
    dim3 gw(4, H / 32, 3);      // fused-3 weight GEMM, M=256 (96 CTAs)

    setup_kernel<<<139, 256>>>(rule_adj, Ab, rsb, x, We, be, hb, msg_b2, upd_W1, c2b);

    // W2u[l] = msg_W2[l] @ upd_W1b[l]
    gemm_kernel<<<gw, 128>>>(
        mkjob(msg_W2 + 0 * HH, upd_W1 + 0 * 2 * HH + HH, w2ub + 0 * HH),
        mkjob(msg_W2 + 1 * HH, upd_W1 + 1 * 2 * HH + HH, w2ub + 1 * HH),
        mkjob(msg_W2 + 2 * HH, upd_W1 + 2 * 2 * HH + HH, w2ub + 2 * HH));

    for (int l = 0; l < L; l++) {
        const float* W1a = msg_W1 + l * 2 * HH;
        const float* W1b = W1a + HH;
        // fused: aact = h@W1a ; bb = h@W1b + b1 ; hu = h@Wu1a + b1u + rs*c2
        gemm_kernel<<<g3, 128>>>(
            mkjob(hb, W1a, aact),
            mkjob(hb, W1b, bbb, msg_b1 + l * H),
            mkjob(hb, upd_W1 + l * 2 * HH, hub, upd_b1 + l * H, rsb, c2b + l * H));
        agg_kernel<<<dim3(4, 8, B), 128>>>(aact, bbb, Ab, aggb);
        // upre = relu(agg@W2u + hu)
        {
            GemmJob j = mkjob(aggb, w2ub + l * HH, upreb, nullptr, nullptr, nullptr, hub, 1);
            gemm_kernel<<<g1, 128>>>(j, j, j);
        }
        // u = upre@Wu2 + b2u
        {
            GemmJob j = mkjob(upreb, upd_W2 + l * HH, ub, upd_b2 + l * H);
            gemm_kernel<<<g1, 128>>>(j, j, j);
        }
        ln_kernel<<<M, H>>>(hb, ub, ln_g + l * H, ln_b + l * H);
    }

    // fused q/k/v
    gemm_kernel<<<g3, 128>>>(
        mkjob(hb, Wq, qb, bq),
        mkjob(hb, Wk, kb, bk),
        mkjob(hb, Wv, vb, bv));
    attn_kernel<<<dim3(R / 16, NH, B), 256>>>(qb, kb, vb, aob);
    readout_kernel<<<B, H>>>(aob, Wo, bo, roW1, rob1, roW2, rob2, out);
    (void)in_sizes; (void)n_in; (void)out_size;
}